// round 16
// baseline (speedup 1.0000x reference)
#include <cuda_runtime.h>
#include <cuda_fp16.h>
#include <math.h>
#include <stdint.h>

// Problem constants (MixtureOfExperts_67010079752265)
#define TOK_MAX 8192
#define DIM     1024
#define NEXP    4
#define HID     4096

// GEMM tiling (mma.sync m16n8k16 fp16, fp32 accum)
// CTA tile 128x128, TK=64, 256 threads (8 warps, warp tile 32x64), 2 CTAs/SM
#define TM 128
#define TN 128
#define TK 64
#define NTHR 256
#define NSTAGE 3
#define A_STR 144                 // bytes per A smem row (64 halfs + 8 pad)
#define ASZ   (128 * 144)         // 18432
#define BOFF  ASZ
#define B_STR 272                 // bytes per B smem row (128 halfs + 8 pad)
#define BSZ   (64 * 272)          // 17408
#define SBUF  (ASZ + BSZ)         // 35840
#define SMEM_DYN (NSTAGE * SBUF)  // 107520 (2 CTAs/SM -> 215KB/SM)

// ---------------- device scratch ----------------
__device__ int   g_cnt[NEXP];
__device__ int   g_tok[NEXP * TOK_MAX];
__device__ float g_wt [NEXP * TOK_MAX];
__device__ __align__(16) __half g_x_h [(size_t)TOK_MAX * DIM];
__device__ __align__(16) __half g_w1_h[(size_t)NEXP * DIM * HID];   // [e][k=D][n=H]
__device__ __align__(16) __half g_w2_h[(size_t)NEXP * HID * DIM];   // [e][k=H][n=D]
__device__ __align__(16) __half g_h_h [(size_t)NEXP * TOK_MAX * HID];

// ---------------- helpers ----------------
__device__ __forceinline__ uint32_t smem_u32(const void* p) {
    return (uint32_t)__cvta_generic_to_shared(p);
}
__device__ __forceinline__ void cp16(uint32_t dst, const void* src) {
    asm volatile("cp.async.cg.shared.global [%0], [%1], 16;"
                 :: "r"(dst), "l"(src) : "memory");
}
__device__ __forceinline__ void cp_commit() {
    asm volatile("cp.async.commit_group;" ::: "memory");
}
__device__ __forceinline__ void cp_wait1() {
    asm volatile("cp.async.wait_group 1;" ::: "memory");
}

#define LDSM_X4(r, addr) \
    asm volatile("ldmatrix.sync.aligned.m8n8.x4.shared.b16 {%0,%1,%2,%3}, [%4];" \
                 : "=r"((r)[0]), "=r"((r)[1]), "=r"((r)[2]), "=r"((r)[3]) : "r"(addr))
#define LDSM_X4T(r, addr) \
    asm volatile("ldmatrix.sync.aligned.m8n8.x4.trans.shared.b16 {%0,%1,%2,%3}, [%4];" \
                 : "=r"((r)[0]), "=r"((r)[1]), "=r"((r)[2]), "=r"((r)[3]) : "r"(addr))
#define MMA_F16(d, a, b0, b1) \
    asm volatile("mma.sync.aligned.m16n8k16.row.col.f32.f16.f16.f32 " \
                 "{%0,%1,%2,%3},{%4,%5,%6,%7},{%8,%9},{%0,%1,%2,%3};" \
                 : "+f"((d)[0]), "+f"((d)[1]), "+f"((d)[2]), "+f"((d)[3]) \
                 : "r"((a)[0]), "r"((a)[1]), "r"((a)[2]), "r"((a)[3]), \
                   "r"(b0), "r"(b1))

__device__ __forceinline__ uint32_t pack2h(__half a, __half b) {
    return (uint32_t)__half_as_ushort(a) | ((uint32_t)__half_as_ushort(b) << 16);
}
__device__ __forceinline__ uint2 cvt_f4(float4 v) {
    return make_uint2(pack2h(__float2half(v.x), __float2half(v.y)),
                      pack2h(__float2half(v.z), __float2half(v.w)));
}

// ---------------- fused preprocess: router (blocks 0..8191) + weight conv ----
#define NW4      (NEXP * DIM * HID / 4)       // 4M float4 per weight tensor
#define RBLKS    TOK_MAX                       // router blocks
#define F4_PER_BLK 1024                        // conv: 1024 float4 per block (128 thr x 8)
#define CBLKS    ((2 * NW4) / F4_PER_BLK)      // 8192 conv blocks
__global__ void __launch_bounds__(128)
pre_kernel(const float* __restrict__ x,  const float* __restrict__ Wr,
           const float* __restrict__ W1, const float* __restrict__ W2) {
    const int tid = threadIdx.x;
    if (blockIdx.x >= RBLKS) {
        // ---- weight conversion: 8 float4 per thread, MLP=8 ----
        // NW4 % F4_PER_BLK == 0, so a block never straddles the W1/W2 boundary.
        int base = (blockIdx.x - RBLKS) * F4_PER_BLK;
        const float4* src;
        uint2* dst;
        if (base < NW4) { src = (const float4*)W1; dst = (uint2*)g_w1_h; }
        else            { src = (const float4*)W2; dst = (uint2*)g_w2_h; base -= NW4; }
        float4 v[8];
        #pragma unroll
        for (int i = 0; i < 8; i++) v[i] = src[base + tid + i * 128];
        #pragma unroll
        for (int i = 0; i < 8; i++) dst[base + tid + i * 128] = cvt_f4(v[i]);
        return;
    }
    // ---- router (also emits x in fp16) ----
    const int t = blockIdx.x;
    float acc0 = 0.f, acc1 = 0.f, acc2 = 0.f, acc3 = 0.f;
    const float4* wr4 = (const float4*)Wr;
    const float*  xr  = x + (size_t)t * DIM;
    uint2* xh = (uint2*)(g_x_h + (size_t)t * DIM);
    for (int d0 = tid * 4; d0 < DIM; d0 += 512) {
        float4 xv = *(const float4*)(xr + d0);
        xh[d0 >> 2] = cvt_f4(xv);
        float4 w0 = wr4[d0], w1 = wr4[d0 + 1], w2 = wr4[d0 + 2], w3 = wr4[d0 + 3];
        acc0 = fmaf(xv.x, w0.x, fmaf(xv.y, w1.x, fmaf(xv.z, w2.x, fmaf(xv.w, w3.x, acc0))));
        acc1 = fmaf(xv.x, w0.y, fmaf(xv.y, w1.y, fmaf(xv.z, w2.y, fmaf(xv.w, w3.y, acc1))));
        acc2 = fmaf(xv.x, w0.z, fmaf(xv.y, w1.z, fmaf(xv.z, w2.z, fmaf(xv.w, w3.z, acc2))));
        acc3 = fmaf(xv.x, w0.w, fmaf(xv.y, w1.w, fmaf(xv.z, w2.w, fmaf(xv.w, w3.w, acc3))));
    }
    __shared__ float sr[4][128];
    sr[0][tid] = acc0; sr[1][tid] = acc1; sr[2][tid] = acc2; sr[3][tid] = acc3;
    __syncthreads();
    for (int s = 64; s > 0; s >>= 1) {
        if (tid < s) {
            sr[0][tid] += sr[0][tid + s];
            sr[1][tid] += sr[1][tid + s];
            sr[2][tid] += sr[2][tid + s];
            sr[3][tid] += sr[3][tid + s];
        }
        __syncthreads();
    }
    if (tid == 0) {
        float l[4] = { sr[0][0], sr[1][0], sr[2][0], sr[3][0] };
        int i0 = 0;
        #pragma unroll
        for (int e = 1; e < 4; e++) if (l[e] > l[i0]) i0 = e;
        int i1 = -1;
        #pragma unroll
        for (int e = 0; e < 4; e++) {
            if (e == i0) continue;
            if (i1 < 0 || l[e] > l[i1]) i1 = e;
        }
        float e1 = expf(l[i1] - l[i0]);
        float w0 = 1.0f / (1.0f + e1);
        float w1 = e1 / (1.0f + e1);
        int s0 = atomicAdd(&g_cnt[i0], 1);
        g_tok[i0 * TOK_MAX + s0] = t;
        g_wt [i0 * TOK_MAX + s0] = w0;
        int s1 = atomicAdd(&g_cnt[i1], 1);
        g_tok[i1 * TOK_MAX + s1] = t;
        g_wt [i1 * TOK_MAX + s1] = w1;
    }
}

// ---------------- GEMM1: h = relu(Xg @ W1_e + b1_e), fp16 mma ----------------
__global__ void __launch_bounds__(NTHR, 2)
gemm1_mma(const float* __restrict__ b1) {
    extern __shared__ __align__(16) char smem[];
    const int e   = blockIdx.z;
    const int cnt = g_cnt[e];
    const int m0  = blockIdx.x * TM;
    if (m0 >= cnt) return;
    const int n0  = blockIdx.y * TN;
    const int t    = threadIdx.x;
    const int wid  = t >> 5;
    const int lane = t & 31;
    const int wm0  = (wid >> 1) * 32;
    const int wn0  = (wid & 1) * 64;
    const uint32_t sbase = smem_u32(smem);

    const int arow = t >> 1;
    const int aseg = t & 1;
    const int slotA = m0 + arow;
    const int tokA = g_tok[e * TOK_MAX + (slotA < cnt ? slotA : 0)];
    const size_t   aOff = (size_t)tokA * DIM + aseg * 32;
    const uint32_t aDst = (uint32_t)(arow * A_STR + aseg * 64);
    const int brow = t >> 2;
    const int bseg = t & 3;
    const size_t   bOff = ((size_t)e * DIM + brow) * HID + n0 + bseg * 32;
    const uint32_t bDst = (uint32_t)(BOFF + brow * B_STR + bseg * 64);

    auto load_A = [&](int buf, int k0) {
        uint32_t bb = sbase + buf * SBUF;
        const __half* ap = g_x_h + aOff + k0;
        #pragma unroll
        for (int i = 0; i < 4; i++) cp16(bb + aDst + i * 16, ap + i * 8);
    };
    auto load_B = [&](int buf, int k0) {
        uint32_t bb = sbase + buf * SBUF;
        const __half* bp = g_w1_h + bOff + (size_t)k0 * HID;
        #pragma unroll
        for (int i = 0; i < 4; i++) cp16(bb + bDst + i * 16, bp + i * 8);
    };

    float d[2][8][4];
    #pragma unroll
    for (int i = 0; i < 2; i++)
        #pragma unroll
        for (int j = 0; j < 8; j++)
            #pragma unroll
            for (int q = 0; q < 4; q++) d[i][j][q] = 0.f;

    const uint32_t aFrag = (wm0 + (lane & 15)) * A_STR + (lane >> 4) * 16;
    const uint32_t bFrag = (lane & 15) * B_STR + wn0 * 2 + (lane >> 4) * 16;

    const int NC = DIM / TK;   // 16
    load_A(0, 0);  load_B(0, 0);  cp_commit();
    load_A(1, TK); load_B(1, TK); cp_commit();
    cp_wait1();
    __syncthreads();

    for (int ch = 0; ch < NC; ch++) {
        const int buf  = ch % NSTAGE;
        const bool pf  = (ch + 2 < NC);
        const int kn   = (ch + 2) * TK;
        const int nbuf = (ch + 2) % NSTAGE;

        const uint32_t Ab = sbase + buf * SBUF + aFrag;
        const uint32_t Bb = sbase + buf * SBUF + BOFF + bFrag;

        uint32_t af[2][2][4];
        uint32_t bf[2][4][4];
        #pragma unroll
        for (int mi = 0; mi < 2; mi++) LDSM_X4(af[0][mi], Ab + mi * 16 * A_STR);
        #pragma unroll
        for (int nj = 0; nj < 4; nj++) LDSM_X4T(bf[0][nj], Bb + nj * 32);

        #pragma unroll
        for (int ks = 0; ks < 4; ks++) {
            const int cur = ks & 1, nxt = cur ^ 1;
            if (ks == 0 && pf) load_A(nbuf, kn);
            if (ks == 2 && pf) load_B(nbuf, kn);
            if (ks < 3) {
                #pragma unroll
                for (int mi = 0; mi < 2; mi++)
                    LDSM_X4(af[nxt][mi], Ab + mi * 16 * A_STR + (ks + 1) * 32);
                #pragma unroll
                for (int nj = 0; nj < 4; nj++)
                    LDSM_X4T(bf[nxt][nj], Bb + (ks + 1) * 16 * B_STR + nj * 32);
            }
            #pragma unroll
            for (int nj = 0; nj < 4; nj++) {
                #pragma unroll
                for (int mi = 0; mi < 2; mi++) {
                    MMA_F16(d[mi][2 * nj],     af[cur][mi], bf[cur][nj][0], bf[cur][nj][1]);
                    MMA_F16(d[mi][2 * nj + 1], af[cur][mi], bf[cur][nj][2], bf[cur][nj][3]);
                }
            }
        }
        if (ch + 1 < NC) {
            cp_commit();
            cp_wait1();
            __syncthreads();
        }
    }

    // epilogue: bias + relu -> fp16 h (indexed by slot)
    const int trow = lane >> 2;
    const int tcol = 2 * (lane & 3);
    #pragma unroll
    for (int mi = 0; mi < 2; mi++) {
        #pragma unroll
        for (int h2 = 0; h2 < 2; h2++) {
            int slot = m0 + wm0 + mi * 16 + trow + h2 * 8;
            if (slot < cnt) {
                size_t hb = ((size_t)e * TOK_MAX + slot) * HID;
                #pragma unroll
                for (int ni = 0; ni < 8; ni++) {
                    int col = n0 + wn0 + ni * 8 + tcol;
                    float v0 = fmaxf(d[mi][ni][h2 * 2 + 0] + __ldg(&b1[e * HID + col]),     0.f);
                    float v1 = fmaxf(d[mi][ni][h2 * 2 + 1] + __ldg(&b1[e * HID + col + 1]), 0.f);
                    *(uint32_t*)(g_h_h + hb + col) = pack2h(__float2half(v0), __float2half(v1));
                }
            }
        }
    }
}

// ---------------- GEMM2: out[tok] += w*(h @ W2_e + b2_e), fp16 mma, split-K=2 ----
__global__ void __launch_bounds__(NTHR, 2)
gemm2_mma(const float* __restrict__ b2, float* __restrict__ out) {
    extern __shared__ __align__(16) char smem[];
    const int e     = blockIdx.z >> 1;
    const int khalf = blockIdx.z & 1;
    const int cnt = g_cnt[e];
    const int m0  = blockIdx.x * TM;
    if (m0 >= cnt) return;
    const int n0  = blockIdx.y * TN;
    const int kb  = khalf * (HID / 2);
    const int t    = threadIdx.x;
    const int wid  = t >> 5;
    const int lane = t & 31;
    const int wm0  = (wid >> 1) * 32;
    const int wn0  = (wid & 1) * 64;
    const uint32_t sbase = smem_u32(smem);

    const int arow = t >> 1;
    const int aseg = t & 1;
    const size_t   aOff = ((size_t)e * TOK_MAX + m0 + arow) * HID + kb + aseg * 32;
    const uint32_t aDst = (uint32_t)(arow * A_STR + aseg * 64);
    const int brow = t >> 2;
    const int bseg = t & 3;
    const size_t   bOff = ((size_t)e * HID + kb + brow) * DIM + n0 + bseg * 32;
    const uint32_t bDst = (uint32_t)(BOFF + brow * B_STR + bseg * 64);

    auto load_A = [&](int buf, int k0) {
        uint32_t bb = sbase + buf * SBUF;
        const __half* ap = g_h_h + aOff + k0;
        #pragma unroll
        for (int i = 0; i < 4; i++) cp16(bb + aDst + i * 16, ap + i * 8);
    };
    auto load_B = [&](int buf, int k0) {
        uint32_t bb = sbase + buf * SBUF;
        const __half* bp = g_w2_h + bOff + (size_t)k0 * DIM;
        #pragma unroll
        for (int i = 0; i < 4; i++) cp16(bb + bDst + i * 16, bp + i * 8);
    };

    float d[2][8][4];
    #pragma unroll
    for (int i = 0; i < 2; i++)
        #pragma unroll
        for (int j = 0; j < 8; j++)
            #pragma unroll
            for (int q = 0; q < 4; q++) d[i][j][q] = 0.f;

    const uint32_t aFrag = (wm0 + (lane & 15)) * A_STR + (lane >> 4) * 16;
    const uint32_t bFrag = (lane & 15) * B_STR + wn0 * 2 + (lane >> 4) * 16;

    const int NC = (HID / 2) / TK;   // 32
    load_A(0, 0);  load_B(0, 0);  cp_commit();
    load_A(1, TK); load_B(1, TK); cp_commit();
    cp_wait1();
    __syncthreads();

    for (int ch = 0; ch < NC; ch++) {
        const int buf  = ch % NSTAGE;
        const bool pf  = (ch + 2 < NC);
        const int kn   = (ch + 2) * TK;
        const int nbuf = (ch + 2) % NSTAGE;

        const uint32_t Ab = sbase + buf * SBUF + aFrag;
        const uint32_t Bb = sbase + buf * SBUF + BOFF + bFrag;

        uint32_t af[2][2][4];
        uint32_t bf[2][4][4];
        #pragma unroll
        for (int mi = 0; mi < 2; mi++) LDSM_X4(af[0][mi], Ab + mi * 16 * A_STR);
        #pragma unroll
        for (int nj = 0; nj < 4; nj++) LDSM_X4T(bf[0][nj], Bb + nj * 32);

        #pragma unroll
        for (int ks = 0; ks < 4; ks++) {
            const int cur = ks & 1, nxt = cur ^ 1;
            if (ks == 0 && pf) load_A(nbuf, kn);
            if (ks == 2 && pf) load_B(nbuf, kn);
            if (ks < 3) {
                #pragma unroll
                for (int mi = 0; mi < 2; mi++)
                    LDSM_X4(af[nxt][mi], Ab + mi * 16 * A_STR + (ks + 1) * 32);
                #pragma unroll
                for (int nj = 0; nj < 4; nj++)
                    LDSM_X4T(bf[nxt][nj], Bb + (ks + 1) * 16 * B_STR + nj * 32);
            }
            #pragma unroll
            for (int nj = 0; nj < 4; nj++) {
                #pragma unroll
                for (int mi = 0; mi < 2; mi++) {
                    MMA_F16(d[mi][2 * nj],     af[cur][mi], bf[cur][nj][0], bf[cur][nj][1]);
                    MMA_F16(d[mi][2 * nj + 1], af[cur][mi], bf[cur][nj][2], bf[cur][nj][3]);
                }
            }
        }
        if (ch + 1 < NC) {
            cp_commit();
            cp_wait1();
            __syncthreads();
        }
    }

    // epilogue: wt*(acc [+ b2 if khalf==0]) -> atomicAdd into out
    const int trow = lane >> 2;
    const int tcol = 2 * (lane & 3);
    const float bscale = (khalf == 0) ? 1.f : 0.f;
    #pragma unroll
    for (int mi = 0; mi < 2; mi++) {
        #pragma unroll
        for (int h2 = 0; h2 < 2; h2++) {
            int slot = m0 + wm0 + mi * 16 + trow + h2 * 8;
            if (slot < cnt) {
                int   tok = g_tok[e * TOK_MAX + slot];
                float wt  = g_wt [e * TOK_MAX + slot];
                float* orow = out + (size_t)tok * DIM;
                #pragma unroll
                for (int ni = 0; ni < 8; ni++) {
                    int col = n0 + wn0 + ni * 8 + tcol;
                    atomicAdd(orow + col,     wt * (d[mi][ni][h2 * 2 + 0] + bscale * __ldg(&b2[e * DIM + col])));
                    atomicAdd(orow + col + 1, wt * (d[mi][ni][h2 * 2 + 1] + bscale * __ldg(&b2[e * DIM + col + 1])));
                }
            }
        }
    }
}

// ---------------- launch ----------------
extern "C" void kernel_launch(void* const* d_in, const int* in_sizes, int n_in,
                              void* d_out, int out_size) {
    const float* x  = (const float*)d_in[0];
    const float* Wr = (const float*)d_in[1];
    const float* W1 = (const float*)d_in[2];
    const float* b1 = (const float*)d_in[3];
    const float* W2 = (const float*)d_in[4];
    const float* b2 = (const float*)d_in[5];
    float* out = (float*)d_out;

    cudaFuncSetAttribute(gemm1_mma, cudaFuncAttributeMaxDynamicSharedMemorySize, SMEM_DYN);
    cudaFuncSetAttribute(gemm2_mma, cudaFuncAttributeMaxDynamicSharedMemorySize, SMEM_DYN);

    void* cnt_ptr = nullptr;
    cudaGetSymbolAddress(&cnt_ptr, g_cnt);

    cudaMemsetAsync(out, 0, (size_t)out_size * sizeof(float));   // node 1
    cudaMemsetAsync(cnt_ptr, 0, NEXP * sizeof(int));             // node 2

    pre_kernel<<<RBLKS + CBLKS, 128>>>(x, Wr, W1, W2);           // kernel 1

    dim3 gg1(TOK_MAX / TM, HID / TN, NEXP);       // (64, 32, 4)
    gemm1_mma<<<gg1, NTHR, SMEM_DYN>>>(b1);                      // kernel 2

    dim3 gg2(TOK_MAX / TM, DIM / TN, NEXP * 2);   // (64, 8, 8) split-K=2
    gemm2_mma<<<gg2, NTHR, SMEM_DYN>>>(b2, out);                 // kernel 3
}

// round 17
// speedup vs baseline: 1.0075x; 1.0075x over previous
#include <cuda_runtime.h>
#include <cuda_fp16.h>
#include <math.h>
#include <stdint.h>

// Problem constants (MixtureOfExperts_67010079752265)
#define TOK_MAX 8192
#define DIM     1024
#define NEXP    4
#define HID     4096

// GEMM tiling (mma.sync m16n8k16 fp16, fp32 accum)
// CTA tile 128x128, TK=64, 256 threads (8 warps, warp tile 32x64), 2 CTAs/SM
#define TM 128
#define TN 128
#define TK 64
#define NTHR 256
#define NSTAGE 3
#define A_STR 144                 // bytes per A smem row (64 halfs + 8 pad)
#define ASZ   (128 * 144)         // 18432
#define BOFF  ASZ
#define B_STR 272                 // bytes per B smem row (128 halfs + 8 pad)
#define BSZ   (64 * 272)          // 17408
#define SBUF  (ASZ + BSZ)         // 35840
#define SMEM_DYN (NSTAGE * SBUF)  // 107520 (2 CTAs/SM -> 215KB/SM)

// ---------------- device scratch ----------------
__device__ int   g_cnt[NEXP];
__device__ int   g_tok[NEXP * TOK_MAX];
__device__ float g_wt [NEXP * TOK_MAX];
__device__ __align__(16) __half g_x_h [(size_t)TOK_MAX * DIM];
__device__ __align__(16) __half g_w1_h[(size_t)NEXP * DIM * HID];   // [e][k=D][n=H]
__device__ __align__(16) __half g_w2_h[(size_t)NEXP * HID * DIM];   // [e][k=H][n=D]
__device__ __align__(16) __half g_h_h [(size_t)NEXP * TOK_MAX * HID];

// ---------------- helpers ----------------
__device__ __forceinline__ uint32_t smem_u32(const void* p) {
    return (uint32_t)__cvta_generic_to_shared(p);
}
__device__ __forceinline__ void cp16(uint32_t dst, const void* src) {
    asm volatile("cp.async.cg.shared.global [%0], [%1], 16;"
                 :: "r"(dst), "l"(src) : "memory");
}
__device__ __forceinline__ void cp_commit() {
    asm volatile("cp.async.commit_group;" ::: "memory");
}
__device__ __forceinline__ void cp_wait1() {
    asm volatile("cp.async.wait_group 1;" ::: "memory");
}

#define LDSM_X4(r, addr) \
    asm volatile("ldmatrix.sync.aligned.m8n8.x4.shared.b16 {%0,%1,%2,%3}, [%4];" \
                 : "=r"((r)[0]), "=r"((r)[1]), "=r"((r)[2]), "=r"((r)[3]) : "r"(addr))
#define LDSM_X4T(r, addr) \
    asm volatile("ldmatrix.sync.aligned.m8n8.x4.trans.shared.b16 {%0,%1,%2,%3}, [%4];" \
                 : "=r"((r)[0]), "=r"((r)[1]), "=r"((r)[2]), "=r"((r)[3]) : "r"(addr))
#define MMA_F16(d, a, b0, b1) \
    asm volatile("mma.sync.aligned.m16n8k16.row.col.f32.f16.f16.f32 " \
                 "{%0,%1,%2,%3},{%4,%5,%6,%7},{%8,%9},{%0,%1,%2,%3};" \
                 : "+f"((d)[0]), "+f"((d)[1]), "+f"((d)[2]), "+f"((d)[3]) \
                 : "r"((a)[0]), "r"((a)[1]), "r"((a)[2]), "r"((a)[3]), \
                   "r"(b0), "r"(b1))

__device__ __forceinline__ uint32_t pack2h(__half a, __half b) {
    return (uint32_t)__half_as_ushort(a) | ((uint32_t)__half_as_ushort(b) << 16);
}
__device__ __forceinline__ uint2 cvt_f4(float4 v) {
    return make_uint2(pack2h(__float2half(v.x), __float2half(v.y)),
                      pack2h(__float2half(v.z), __float2half(v.w)));
}

// ---------------- preprocess: router (blocks 0..8191) + W1 conversion ------
#define NW4      (NEXP * DIM * HID / 4)       // 4M float4 per weight tensor
#define RBLKS    TOK_MAX                       // router blocks
#define F4_PER_BLK 1024                        // W1 conv: 1024 float4 per block
#define CBLKS    (NW4 / F4_PER_BLK)            // 4096 conv blocks (W1 only)
__global__ void __launch_bounds__(128)
pre_kernel(const float* __restrict__ x,  const float* __restrict__ Wr,
           const float* __restrict__ W1) {
    const int tid = threadIdx.x;
    if (blockIdx.x >= RBLKS) {
        // ---- W1 conversion: 8 float4 per thread, MLP=8 ----
        int base = (blockIdx.x - RBLKS) * F4_PER_BLK;
        const float4* src = (const float4*)W1;
        uint2* dst = (uint2*)g_w1_h;
        float4 v[8];
        #pragma unroll
        for (int i = 0; i < 8; i++) v[i] = src[base + tid + i * 128];
        #pragma unroll
        for (int i = 0; i < 8; i++) dst[base + tid + i * 128] = cvt_f4(v[i]);
        return;
    }
    // ---- router (also emits x in fp16) ----
    const int t = blockIdx.x;
    float acc0 = 0.f, acc1 = 0.f, acc2 = 0.f, acc3 = 0.f;
    const float4* wr4 = (const float4*)Wr;
    const float*  xr  = x + (size_t)t * DIM;
    uint2* xh = (uint2*)(g_x_h + (size_t)t * DIM);
    for (int d0 = tid * 4; d0 < DIM; d0 += 512) {
        float4 xv = *(const float4*)(xr + d0);
        xh[d0 >> 2] = cvt_f4(xv);
        float4 w0 = wr4[d0], w1 = wr4[d0 + 1], w2 = wr4[d0 + 2], w3 = wr4[d0 + 3];
        acc0 = fmaf(xv.x, w0.x, fmaf(xv.y, w1.x, fmaf(xv.z, w2.x, fmaf(xv.w, w3.x, acc0))));
        acc1 = fmaf(xv.x, w0.y, fmaf(xv.y, w1.y, fmaf(xv.z, w2.y, fmaf(xv.w, w3.y, acc1))));
        acc2 = fmaf(xv.x, w0.z, fmaf(xv.y, w1.z, fmaf(xv.z, w2.z, fmaf(xv.w, w3.z, acc2))));
        acc3 = fmaf(xv.x, w0.w, fmaf(xv.y, w1.w, fmaf(xv.z, w2.w, fmaf(xv.w, w3.w, acc3))));
    }
    __shared__ float sr[4][128];
    sr[0][tid] = acc0; sr[1][tid] = acc1; sr[2][tid] = acc2; sr[3][tid] = acc3;
    __syncthreads();
    for (int s = 64; s > 0; s >>= 1) {
        if (tid < s) {
            sr[0][tid] += sr[0][tid + s];
            sr[1][tid] += sr[1][tid + s];
            sr[2][tid] += sr[2][tid + s];
            sr[3][tid] += sr[3][tid + s];
        }
        __syncthreads();
    }
    if (tid == 0) {
        float l[4] = { sr[0][0], sr[1][0], sr[2][0], sr[3][0] };
        int i0 = 0;
        #pragma unroll
        for (int e = 1; e < 4; e++) if (l[e] > l[i0]) i0 = e;
        int i1 = -1;
        #pragma unroll
        for (int e = 0; e < 4; e++) {
            if (e == i0) continue;
            if (i1 < 0 || l[e] > l[i1]) i1 = e;
        }
        float e1 = expf(l[i1] - l[i0]);
        float w0 = 1.0f / (1.0f + e1);
        float w1 = e1 / (1.0f + e1);
        int s0 = atomicAdd(&g_cnt[i0], 1);
        g_tok[i0 * TOK_MAX + s0] = t;
        g_wt [i0 * TOK_MAX + s0] = w0;
        int s1 = atomicAdd(&g_cnt[i1], 1);
        g_tok[i1 * TOK_MAX + s1] = t;
        g_wt [i1 * TOK_MAX + s1] = w1;
    }
}

// ---------------- GEMM1: h = relu(Xg @ W1_e + b1_e), fp16 mma --------------
// blockIdx.z == NEXP -> W2 conversion arm (hides under tensor-bound GEMM CTAs;
// same-kernel completion guarantees W2 ready before gemm2 launches).
#define W2_CONV_BLKS (TOK_MAX / TM * (HID / TN))   // 2048 (= grid x*y)
#define W2_F4_PER_BLK (NW4 / W2_CONV_BLKS)         // 2048 float4 per block
__global__ void __launch_bounds__(NTHR, 2)
gemm1_mma(const float* __restrict__ b1, const float* __restrict__ W2) {
    const int t = threadIdx.x;
    if (blockIdx.z == NEXP) {
        // ---- W2 conversion: 2048 f4 / block, 256 thr, batches of 4 (MLP=4x2) ----
        int base = (blockIdx.y * gridDim.x + blockIdx.x) * W2_F4_PER_BLK;
        const float4* src = (const float4*)W2;
        uint2* dst = (uint2*)g_w2_h;
        #pragma unroll
        for (int r = 0; r < W2_F4_PER_BLK / (NTHR * 4); r++) {   // 2 rounds
            float4 v[4];
            #pragma unroll
            for (int i = 0; i < 4; i++)
                v[i] = src[base + r * NTHR * 4 + i * NTHR + t];
            #pragma unroll
            for (int i = 0; i < 4; i++)
                dst[base + r * NTHR * 4 + i * NTHR + t] = cvt_f4(v[i]);
        }
        return;
    }
    extern __shared__ __align__(16) char smem[];
    const int e   = blockIdx.z;
    const int cnt = g_cnt[e];
    const int m0  = blockIdx.x * TM;
    if (m0 >= cnt) return;
    const int n0  = blockIdx.y * TN;
    const int wid  = t >> 5;
    const int lane = t & 31;
    const int wm0  = (wid >> 1) * 32;
    const int wn0  = (wid & 1) * 64;
    const uint32_t sbase = smem_u32(smem);

    const int arow = t >> 1;
    const int aseg = t & 1;
    const int slotA = m0 + arow;
    const int tokA = g_tok[e * TOK_MAX + (slotA < cnt ? slotA : 0)];
    const size_t   aOff = (size_t)tokA * DIM + aseg * 32;
    const uint32_t aDst = (uint32_t)(arow * A_STR + aseg * 64);
    const int brow = t >> 2;
    const int bseg = t & 3;
    const size_t   bOff = ((size_t)e * DIM + brow) * HID + n0 + bseg * 32;
    const uint32_t bDst = (uint32_t)(BOFF + brow * B_STR + bseg * 64);

    auto load_A = [&](int buf, int k0) {
        uint32_t bb = sbase + buf * SBUF;
        const __half* ap = g_x_h + aOff + k0;
        #pragma unroll
        for (int i = 0; i < 4; i++) cp16(bb + aDst + i * 16, ap + i * 8);
    };
    auto load_B = [&](int buf, int k0) {
        uint32_t bb = sbase + buf * SBUF;
        const __half* bp = g_w1_h + bOff + (size_t)k0 * HID;
        #pragma unroll
        for (int i = 0; i < 4; i++) cp16(bb + bDst + i * 16, bp + i * 8);
    };

    float d[2][8][4];
    #pragma unroll
    for (int i = 0; i < 2; i++)
        #pragma unroll
        for (int j = 0; j < 8; j++)
            #pragma unroll
            for (int q = 0; q < 4; q++) d[i][j][q] = 0.f;

    const uint32_t aFrag = (wm0 + (lane & 15)) * A_STR + (lane >> 4) * 16;
    const uint32_t bFrag = (lane & 15) * B_STR + wn0 * 2 + (lane >> 4) * 16;

    const int NC = DIM / TK;   // 16
    load_A(0, 0);  load_B(0, 0);  cp_commit();
    load_A(1, TK); load_B(1, TK); cp_commit();
    cp_wait1();
    __syncthreads();

    for (int ch = 0; ch < NC; ch++) {
        const int buf  = ch % NSTAGE;
        const bool pf  = (ch + 2 < NC);
        const int kn   = (ch + 2) * TK;
        const int nbuf = (ch + 2) % NSTAGE;

        const uint32_t Ab = sbase + buf * SBUF + aFrag;
        const uint32_t Bb = sbase + buf * SBUF + BOFF + bFrag;

        uint32_t af[2][2][4];
        uint32_t bf[2][4][4];
        #pragma unroll
        for (int mi = 0; mi < 2; mi++) LDSM_X4(af[0][mi], Ab + mi * 16 * A_STR);
        #pragma unroll
        for (int nj = 0; nj < 4; nj++) LDSM_X4T(bf[0][nj], Bb + nj * 32);

        #pragma unroll
        for (int ks = 0; ks < 4; ks++) {
            const int cur = ks & 1, nxt = cur ^ 1;
            if (ks == 0 && pf) load_A(nbuf, kn);
            if (ks == 2 && pf) load_B(nbuf, kn);
            if (ks < 3) {
                #pragma unroll
                for (int mi = 0; mi < 2; mi++)
                    LDSM_X4(af[nxt][mi], Ab + mi * 16 * A_STR + (ks + 1) * 32);
                #pragma unroll
                for (int nj = 0; nj < 4; nj++)
                    LDSM_X4T(bf[nxt][nj], Bb + (ks + 1) * 16 * B_STR + nj * 32);
            }
            #pragma unroll
            for (int nj = 0; nj < 4; nj++) {
                #pragma unroll
                for (int mi = 0; mi < 2; mi++) {
                    MMA_F16(d[mi][2 * nj],     af[cur][mi], bf[cur][nj][0], bf[cur][nj][1]);
                    MMA_F16(d[mi][2 * nj + 1], af[cur][mi], bf[cur][nj][2], bf[cur][nj][3]);
                }
            }
        }
        if (ch + 1 < NC) {
            cp_commit();
            cp_wait1();
            __syncthreads();
        }
    }

    // epilogue: bias + relu -> fp16 h (indexed by slot)
    const int trow = lane >> 2;
    const int tcol = 2 * (lane & 3);
    #pragma unroll
    for (int mi = 0; mi < 2; mi++) {
        #pragma unroll
        for (int h2 = 0; h2 < 2; h2++) {
            int slot = m0 + wm0 + mi * 16 + trow + h2 * 8;
            if (slot < cnt) {
                size_t hb = ((size_t)e * TOK_MAX + slot) * HID;
                #pragma unroll
                for (int ni = 0; ni < 8; ni++) {
                    int col = n0 + wn0 + ni * 8 + tcol;
                    float v0 = fmaxf(d[mi][ni][h2 * 2 + 0] + __ldg(&b1[e * HID + col]),     0.f);
                    float v1 = fmaxf(d[mi][ni][h2 * 2 + 1] + __ldg(&b1[e * HID + col + 1]), 0.f);
                    *(uint32_t*)(g_h_h + hb + col) = pack2h(__float2half(v0), __float2half(v1));
                }
            }
        }
    }
}

// ---------------- GEMM2: out[tok] += w*(h @ W2_e + b2_e), fp16 mma, split-K=2 ----
__global__ void __launch_bounds__(NTHR, 2)
gemm2_mma(const float* __restrict__ b2, float* __restrict__ out) {
    extern __shared__ __align__(16) char smem[];
    const int e     = blockIdx.z >> 1;
    const int khalf = blockIdx.z & 1;
    const int cnt = g_cnt[e];
    const int m0  = blockIdx.x * TM;
    if (m0 >= cnt) return;
    const int n0  = blockIdx.y * TN;
    const int kb  = khalf * (HID / 2);
    const int t    = threadIdx.x;
    const int wid  = t >> 5;
    const int lane = t & 31;
    const int wm0  = (wid >> 1) * 32;
    const int wn0  = (wid & 1) * 64;
    const uint32_t sbase = smem_u32(smem);

    const int arow = t >> 1;
    const int aseg = t & 1;
    const size_t   aOff = ((size_t)e * TOK_MAX + m0 + arow) * HID + kb + aseg * 32;
    const uint32_t aDst = (uint32_t)(arow * A_STR + aseg * 64);
    const int brow = t >> 2;
    const int bseg = t & 3;
    const size_t   bOff = ((size_t)e * HID + kb + brow) * DIM + n0 + bseg * 32;
    const uint32_t bDst = (uint32_t)(BOFF + brow * B_STR + bseg * 64);

    auto load_A = [&](int buf, int k0) {
        uint32_t bb = sbase + buf * SBUF;
        const __half* ap = g_h_h + aOff + k0;
        #pragma unroll
        for (int i = 0; i < 4; i++) cp16(bb + aDst + i * 16, ap + i * 8);
    };
    auto load_B = [&](int buf, int k0) {
        uint32_t bb = sbase + buf * SBUF;
        const __half* bp = g_w2_h + bOff + (size_t)k0 * DIM;
        #pragma unroll
        for (int i = 0; i < 4; i++) cp16(bb + bDst + i * 16, bp + i * 8);
    };

    float d[2][8][4];
    #pragma unroll
    for (int i = 0; i < 2; i++)
        #pragma unroll
        for (int j = 0; j < 8; j++)
            #pragma unroll
            for (int q = 0; q < 4; q++) d[i][j][q] = 0.f;

    const uint32_t aFrag = (wm0 + (lane & 15)) * A_STR + (lane >> 4) * 16;
    const uint32_t bFrag = (lane & 15) * B_STR + wn0 * 2 + (lane >> 4) * 16;

    const int NC = (HID / 2) / TK;   // 32
    load_A(0, 0);  load_B(0, 0);  cp_commit();
    load_A(1, TK); load_B(1, TK); cp_commit();
    cp_wait1();
    __syncthreads();

    for (int ch = 0; ch < NC; ch++) {
        const int buf  = ch % NSTAGE;
        const bool pf  = (ch + 2 < NC);
        const int kn   = (ch + 2) * TK;
        const int nbuf = (ch + 2) % NSTAGE;

        const uint32_t Ab = sbase + buf * SBUF + aFrag;
        const uint32_t Bb = sbase + buf * SBUF + BOFF + bFrag;

        uint32_t af[2][2][4];
        uint32_t bf[2][4][4];
        #pragma unroll
        for (int mi = 0; mi < 2; mi++) LDSM_X4(af[0][mi], Ab + mi * 16 * A_STR);
        #pragma unroll
        for (int nj = 0; nj < 4; nj++) LDSM_X4T(bf[0][nj], Bb + nj * 32);

        #pragma unroll
        for (int ks = 0; ks < 4; ks++) {
            const int cur = ks & 1, nxt = cur ^ 1;
            if (ks == 0 && pf) load_A(nbuf, kn);
            if (ks == 2 && pf) load_B(nbuf, kn);
            if (ks < 3) {
                #pragma unroll
                for (int mi = 0; mi < 2; mi++)
                    LDSM_X4(af[nxt][mi], Ab + mi * 16 * A_STR + (ks + 1) * 32);
                #pragma unroll
                for (int nj = 0; nj < 4; nj++)
                    LDSM_X4T(bf[nxt][nj], Bb + (ks + 1) * 16 * B_STR + nj * 32);
            }
            #pragma unroll
            for (int nj = 0; nj < 4; nj++) {
                #pragma unroll
                for (int mi = 0; mi < 2; mi++) {
                    MMA_F16(d[mi][2 * nj],     af[cur][mi], bf[cur][nj][0], bf[cur][nj][1]);
                    MMA_F16(d[mi][2 * nj + 1], af[cur][mi], bf[cur][nj][2], bf[cur][nj][3]);
                }
            }
        }
        if (ch + 1 < NC) {
            cp_commit();
            cp_wait1();
            __syncthreads();
        }
    }

    // epilogue: wt*(acc [+ b2 if khalf==0]) -> atomicAdd into out
    const int trow = lane >> 2;
    const int tcol = 2 * (lane & 3);
    const float bscale = (khalf == 0) ? 1.f : 0.f;
    #pragma unroll
    for (int mi = 0; mi < 2; mi++) {
        #pragma unroll
        for (int h2 = 0; h2 < 2; h2++) {
            int slot = m0 + wm0 + mi * 16 + trow + h2 * 8;
            if (slot < cnt) {
                int   tok = g_tok[e * TOK_MAX + slot];
                float wt  = g_wt [e * TOK_MAX + slot];
                float* orow = out + (size_t)tok * DIM;
                #pragma unroll
                for (int ni = 0; ni < 8; ni++) {
                    int col = n0 + wn0 + ni * 8 + tcol;
                    atomicAdd(orow + col,     wt * (d[mi][ni][h2 * 2 + 0] + bscale * __ldg(&b2[e * DIM + col])));
                    atomicAdd(orow + col + 1, wt * (d[mi][ni][h2 * 2 + 1] + bscale * __ldg(&b2[e * DIM + col + 1])));
                }
            }
        }
    }
}

// ---------------- launch ----------------
extern "C" void kernel_launch(void* const* d_in, const int* in_sizes, int n_in,
                              void* d_out, int out_size) {
    const float* x  = (const float*)d_in[0];
    const float* Wr = (const float*)d_in[1];
    const float* W1 = (const float*)d_in[2];
    const float* b1 = (const float*)d_in[3];
    const float* W2 = (const float*)d_in[4];
    const float* b2 = (const float*)d_in[5];
    float* out = (float*)d_out;

    cudaFuncSetAttribute(gemm1_mma, cudaFuncAttributeMaxDynamicSharedMemorySize, SMEM_DYN);
    cudaFuncSetAttribute(gemm2_mma, cudaFuncAttributeMaxDynamicSharedMemorySize, SMEM_DYN);

    void* cnt_ptr = nullptr;
    cudaGetSymbolAddress(&cnt_ptr, g_cnt);

    cudaMemsetAsync(out, 0, (size_t)out_size * sizeof(float));   // node 1
    cudaMemsetAsync(cnt_ptr, 0, NEXP * sizeof(int));             // node 2

    pre_kernel<<<RBLKS + CBLKS, 128>>>(x, Wr, W1);               // kernel 1

    dim3 gg1(TOK_MAX / TM, HID / TN, NEXP + 1);   // (64, 32, 5): z=4 -> W2 conv
    gemm1_mma<<<gg1, NTHR, SMEM_DYN>>>(b1, W2);                  // kernel 2

    dim3 gg2(TOK_MAX / TM, DIM / TN, NEXP * 2);   // (64, 8, 8) split-K=2
    gemm2_mma<<<gg2, NTHR, SMEM_DYN>>>(b2, out);                 // kernel 3
}